// round 17
// baseline (speedup 1.0000x reference)
#include <cuda_runtime.h>
#include <cuda_bf16.h>
#include <cuda_fp16.h>
#include <math.h>
#include <stdint.h>

#define D 128
#define NF_MAX 50000
#define NP_MAX 12500
#define EF_MAX 600000

// ---------------- scratch (static device globals) ----------------
__device__ __half g_h1[(size_t)NF_MAX * D];   // GEMM0 out (np) / GEMM2 out (nf)
__device__ __half g_h2[(size_t)NP_MAX * D];   // GEMM1 out (compact np)
__device__ float  g_buf2[(size_t)NF_MAX * D]; // gather outputs (fp32 GEMM inputs)
__device__ int    g_cntf[NF_MAX];
__device__ int    g_rpf[NF_MAX + 1];
__device__ int    g_curf[NF_MAX];
__device__ int    g_esrcf[EF_MAX];
__device__ int    g_esrcf2[EF_MAX];           // inv-mapped edge sources for gather1
__device__ float  g_dinvf[NF_MAX];
__device__ int    g_cntp[NP_MAX];
__device__ int    g_rpp[NP_MAX + 1];
__device__ int    g_curp[NP_MAX];
__device__ int    g_esrcp[EF_MAX / 4];
__device__ float  g_dinvp[NP_MAX];
__device__ int    g_inv[NF_MAX];
__device__ int    g_bsf[64];
__device__ int    g_bsp[64];
__device__ unsigned char g_wimg[3][2][32768];

static inline int cdiv(int a, int b) { return (a + b - 1) / b; }

__host__ __device__ __forceinline__ uint32_t swz(int row, int kbyte) {
    return (uint32_t)(row * 256 + (kbyte ^ ((row & 7) << 4)));
}

__device__ __forceinline__ uint32_t smem_u32(const void* p) {
    uint32_t a;
    asm("{ .reg .u64 t; cvta.to.shared.u64 t, %1; cvt.u32.u64 %0, t; }" : "=r"(a) : "l"(p));
    return a;
}
__device__ __forceinline__ void ldmx4(uint32_t* r, uint32_t addr) {
    asm volatile("ldmatrix.sync.aligned.m8n8.x4.shared.b16 {%0,%1,%2,%3}, [%4];"
                 : "=r"(r[0]), "=r"(r[1]), "=r"(r[2]), "=r"(r[3]) : "r"(addr));
}
__device__ __forceinline__ void mma16816(float* c, const uint32_t* a, uint32_t b0, uint32_t b1) {
    asm volatile("mma.sync.aligned.m16n8k16.row.col.f32.bf16.bf16.f32 "
                 "{%0,%1,%2,%3}, {%4,%5,%6,%7}, {%8,%9}, {%0,%1,%2,%3};"
                 : "+f"(c[0]), "+f"(c[1]), "+f"(c[2]), "+f"(c[3])
                 : "r"(a[0]), "r"(a[1]), "r"(a[2]), "r"(a[3]), "r"(b0), "r"(b1));
}

// ================= fused zero + W-prep =================
__global__ void k_zero_prep(int* cntf, int* cntp, int* inv, int nf, int np,
                            const float* __restrict__ W0, const float* __restrict__ W1,
                            const float* __restrict__ W2) {
    int i = blockIdx.x * blockDim.x + threadIdx.x;
    if (i < nf) { cntf[i] = 0; inv[i] = -1; }
    if (i < np) cntp[i] = 0;
    if (i < 3 * 128 * 128) {
        int w = i >> 14, rem = i & 16383;
        int k = rem >> 7, n = rem & 127;
        const float* W = (w == 0) ? W0 : (w == 1) ? W1 : W2;
        float v = W[k * 128 + n];
        __nv_bfloat16 hb = __float2bfloat16(v);
        float r = v - __bfloat162float(hb);
        __nv_bfloat16 lb = __float2bfloat16(r);
        uint32_t sw = swz(n, k * 2);
        *(unsigned short*)(&g_wimg[w][0][sw]) = __bfloat16_as_ushort(hb);
        *(unsigned short*)(&g_wimg[w][1][sw]) = __bfloat16_as_ushort(lb);
    }
}

__global__ void k_inv(const int* __restrict__ unpool, int* __restrict__ inv, int np) {
    int r = blockIdx.x * blockDim.x + threadIdx.x;
    if (r < np) inv[unpool[r]] = r;
}

// ================= single-graph CSR kernels =================
__global__ void k_hist(const int* __restrict__ dst, int E, int* __restrict__ cnt) {
    int e = blockIdx.x * blockDim.x + threadIdx.x;
    if (e < E) atomicAdd(&cnt[dst[e]], 1);
}

__global__ void k_bsum(const int* __restrict__ cnt, int n, int* __restrict__ bs) {
    int b = blockIdx.x;
    int tid = threadIdx.x, lane = tid & 31, warp = tid >> 5;
    int i0 = b * 1024 + tid * 4;
    int s = 0;
#pragma unroll
    for (int k = 0; k < 4; k++) if (i0 + k < n) s += cnt[i0 + k];
#pragma unroll
    for (int off = 16; off > 0; off >>= 1) s += __shfl_down_sync(0xffffffffu, s, off);
    __shared__ int ws[8];
    if (lane == 0) ws[warp] = s;
    __syncthreads();
    if (tid == 0) {
        int t = 0;
#pragma unroll
        for (int w = 0; w < 8; w++) t += ws[w];
        bs[b] = t;
    }
}

// write with inline scan of block sums
__global__ void k_write(const int* __restrict__ cnt, int n, const int* __restrict__ bs, int nb,
                        int* __restrict__ rp, int* __restrict__ cur, float* __restrict__ dinv) {
    __shared__ int sbs[64];
    __shared__ int ws[8];
    int b = blockIdx.x;
    int tid = threadIdx.x, lane = tid & 31, warp = tid >> 5;
    if (tid < 64) sbs[tid] = (tid < nb) ? bs[tid] : 0;
    __syncthreads();
#pragma unroll
    for (int off = 1; off < 64; off <<= 1) {
        int add = (tid >= off && tid < 64) ? sbs[tid - off] : 0;
        __syncthreads();
        if (tid < 64) sbs[tid] += add;
        __syncthreads();
    }
    int i0 = b * 1024 + tid * 4;
    int v[4];
#pragma unroll
    for (int k = 0; k < 4; k++) v[k] = (i0 + k < n) ? cnt[i0 + k] : 0;
    int s = v[0] + v[1] + v[2] + v[3];
    int inc = s;
#pragma unroll
    for (int off = 1; off < 32; off <<= 1) {
        int u = __shfl_up_sync(0xffffffffu, inc, off);
        if (lane >= off) inc += u;
    }
    if (lane == 31) ws[warp] = inc;
    __syncthreads();
    int woff = 0;
#pragma unroll
    for (int w = 0; w < 8; w++) if (w < warp) woff += ws[w];
    int blockoff = b ? sbs[b - 1] : 0;
    int pre = blockoff + woff + inc - s;
#pragma unroll
    for (int k = 0; k < 4; k++) {
        int i = i0 + k;
        if (i < n) {
            rp[i] = pre; cur[i] = pre;
            dinv[i] = rsqrtf((float)v[k] + 1.0f);
            pre += v[k];
        }
    }
    if (b == 0 && tid == 0) rp[n] = sbs[63];
}

__global__ void k_place(const int* __restrict__ src, const int* __restrict__ dst, int E,
                        int* __restrict__ cur, int* __restrict__ esrc) {
    int e = blockIdx.x * blockDim.x + threadIdx.x;
    if (e < E) {
        int p = atomicAdd(&cur[dst[e]], 1);
        esrc[p] = src[e];
    }
}

// place + inv-mapped copy (full graph)
__global__ void k_place2v(const int* __restrict__ src, const int* __restrict__ dst, int E,
                          int* __restrict__ cur, int* __restrict__ esrc,
                          int* __restrict__ esrc2, const int* __restrict__ inv) {
    int e = blockIdx.x * blockDim.x + threadIdx.x;
    if (e < E) {
        int s = src[e];
        int p = atomicAdd(&cur[dst[e]], 1);
        esrc[p] = s;
        esrc2[p] = inv[s];
    }
}

// ================= tensor-core GEMM, M=64 tiles (96KB smem -> 2 blocks/SM) =================
__global__ void __launch_bounds__(256, 1) k_gemm_mma(
    const float* __restrict__ A, const unsigned char* __restrict__ Whi,
    const unsigned char* __restrict__ Wlo, __half* __restrict__ C, int n,
    const float* __restrict__ scale, const int* __restrict__ smap) {
    extern __shared__ unsigned char sm[];
    const int OFF_AHI = 0, OFF_ALO = 16384, OFF_BHI = 32768, OFF_BLO = 65536;
    const uint32_t smb = smem_u32(sm);
    const int tid = threadIdx.x, wid = tid >> 5, lane = tid & 31;
    const int row0 = blockIdx.x * 64;

    for (int i = tid; i < 2048; i += 256) {
        ((float4*)(sm + OFF_BHI))[i] = ((const float4*)Whi)[i];
        ((float4*)(sm + OFF_BLO))[i] = ((const float4*)Wlo)[i];
    }
    {
        int row = tid >> 2, quarter = tid & 3;
        int gr = row0 + row;
        const float4* Arow = (const float4*)(A + (size_t)gr * D) + quarter * 8;
        unsigned char* ahi = sm + OFF_AHI;
        unsigned char* alo = sm + OFF_ALO;
#pragma unroll
        for (int q = 0; q < 8; q++) {
            float4 v = (gr < n) ? Arow[q] : make_float4(0.f, 0.f, 0.f, 0.f);
            float f[4] = {v.x, v.y, v.z, v.w};
#pragma unroll
            for (int p = 0; p < 2; p++) {
                float a0 = f[p * 2], a1 = f[p * 2 + 1];
                __nv_bfloat16 h0 = __float2bfloat16(a0), h1 = __float2bfloat16(a1);
                float r0 = a0 - __bfloat162float(h0);
                float r1 = a1 - __bfloat162float(h1);
                __nv_bfloat16 l0 = __float2bfloat16(r0), l1 = __float2bfloat16(r1);
                uint32_t uhi = (uint32_t)__bfloat16_as_ushort(h0) | ((uint32_t)__bfloat16_as_ushort(h1) << 16);
                uint32_t ulo = (uint32_t)__bfloat16_as_ushort(l0) | ((uint32_t)__bfloat16_as_ushort(l1) << 16);
                int k = quarter * 32 + q * 4 + p * 2;
                uint32_t sw = swz(row, k * 2);
                *(uint32_t*)(ahi + sw) = uhi;
                *(uint32_t*)(alo + sw) = ulo;
            }
        }
    }
    __syncthreads();

    const int rg = wid & 3, ch = wid >> 2;
    const int m0 = rg * 16;
    float acc[8][4];
#pragma unroll
    for (int t = 0; t < 8; t++)
#pragma unroll
        for (int q = 0; q < 4; q++) acc[t][q] = 0.f;

    const int a_row = m0 + (lane & 15);
    const uint32_t a_base = smb + (uint32_t)(a_row * 256);
    const int a_swrow = (a_row & 7) << 4;
    const int a_kadd = (lane >> 4) * 16;
    const int b_rowoff = (lane & 7) + (lane >> 4) * 8;
    const int b_kadd = ((lane >> 3) & 1) * 16;

#pragma unroll 2
    for (int k0 = 0; k0 < 8; k0++) {
        const int kb = k0 * 32;
        uint32_t ahi[4], alo[4];
        uint32_t a_off = (uint32_t)((kb + a_kadd) ^ a_swrow);
        ldmx4(ahi, a_base + OFF_AHI + a_off);
        ldmx4(alo, a_base + OFF_ALO + a_off);
#pragma unroll
        for (int ntp = 0; ntp < 4; ntp++) {
            const int n0 = ch * 64 + ntp * 16;
            const int b_row = n0 + b_rowoff;
            uint32_t b_off = (uint32_t)(b_row * 256 + ((kb + b_kadd) ^ ((b_row & 7) << 4)));
            uint32_t bh[4], bl[4];
            ldmx4(bh, smb + OFF_BHI + b_off);
            ldmx4(bl, smb + OFF_BLO + b_off);
            mma16816(acc[2 * ntp],     ahi, bh[0], bh[1]);
            mma16816(acc[2 * ntp + 1], ahi, bh[2], bh[3]);
            mma16816(acc[2 * ntp],     ahi, bl[0], bl[1]);
            mma16816(acc[2 * ntp + 1], ahi, bl[2], bl[3]);
            mma16816(acc[2 * ntp],     alo, bh[0], bh[1]);
            mma16816(acc[2 * ntp + 1], alo, bh[2], bh[3]);
        }
    }

    const int r_lo = row0 + m0 + (lane >> 2);
    const int cbase = ch * 64 + (lane & 3) * 2;
    if (r_lo < n) {
        float sc = scale ? scale[smap ? smap[r_lo] : r_lo] : 1.0f;
        __half* crow = C + (size_t)r_lo * D;
#pragma unroll
        for (int t = 0; t < 8; t++)
            *(__half2*)(crow + cbase + t * 8) = __floats2half2_rn(acc[t][0] * sc, acc[t][1] * sc);
    }
    const int r_hi = r_lo + 8;
    if (r_hi < n) {
        float sc = scale ? scale[smap ? smap[r_hi] : r_hi] : 1.0f;
        __half* crow = C + (size_t)r_hi * D;
#pragma unroll
        for (int t = 0; t < 8; t++)
            *(__half2*)(crow + cbase + t * 8) = __floats2half2_rn(acc[t][2] * sc, acc[t][3] * sc);
    }
}

// ===== uniform CSR gather: pre-scaled sources, direct (possibly negative) edge indices =====
// out[row] = ELU( (Σ_{s in esrc[rp[row]..]} xw[s] + xw[self]) * dinv[row] + bias )
// self = selfinv ? selfinv[row] : row (negative -> skip).
__global__ void k_gather_s(const int* __restrict__ rp, const int* __restrict__ esrc,
                           const float* __restrict__ dinv, const __half* __restrict__ xw,
                           const float* __restrict__ bias, const int* __restrict__ selfinv,
                           float* __restrict__ out, int n) {
    int row = blockIdx.x * (blockDim.x >> 5) + (threadIdx.x >> 5);
    if (row >= n) return;
    int lane = threadIdx.x & 31;
    float4 acc = make_float4(0.f, 0.f, 0.f, 0.f);
    {
        int sr = selfinv ? selfinv[row] : row;
        if (sr >= 0) {
            uint2 u = reinterpret_cast<const uint2*>(xw + (size_t)sr * D)[lane];
            float2 f0 = __half22float2(*reinterpret_cast<__half2*>(&u.x));
            float2 f1 = __half22float2(*reinterpret_cast<__half2*>(&u.y));
            acc.x = f0.x; acc.y = f0.y; acc.z = f1.x; acc.w = f1.y;
        }
    }
    int s0 = rp[row], s1 = rp[row + 1];
    for (int base = s0; base < s1; base += 32) {
        int cnt = min(32, s1 - base);
        int sid = -1;
        if (lane < cnt) sid = esrc[base + lane];
        for (int j = 0; j < cnt; j++) {
            int s = __shfl_sync(0xffffffffu, sid, j);
            if (s < 0) continue;
            uint2 u = reinterpret_cast<const uint2*>(xw + (size_t)s * D)[lane];
            float2 f0 = __half22float2(*reinterpret_cast<__half2*>(&u.x));
            float2 f1 = __half22float2(*reinterpret_cast<__half2*>(&u.y));
            acc.x += f0.x; acc.y += f0.y; acc.z += f1.x; acc.w += f1.y;
        }
    }
    float di = dinv[row];
    float4 bb = reinterpret_cast<const float4*>(bias)[lane];
    acc.x = acc.x * di + bb.x; acc.y = acc.y * di + bb.y;
    acc.z = acc.z * di + bb.z; acc.w = acc.w * di + bb.w;
    acc.x = acc.x > 0.f ? acc.x : expm1f(acc.x);
    acc.y = acc.y > 0.f ? acc.y : expm1f(acc.y);
    acc.z = acc.z > 0.f ? acc.z : expm1f(acc.z);
    acc.w = acc.w > 0.f ? acc.w : expm1f(acc.w);
    reinterpret_cast<float4*>(out)[(size_t)row * 32 + lane] = acc;
}

extern "C" void kernel_launch(void* const* d_in, const int* in_sizes, int n_in,
                              void* d_out, int out_size) {
    const int*   ei     = (const int*)d_in[1];
    const float* px     = (const float*)d_in[2];
    const int*   pei    = (const int*)d_in[3];
    const int*   unpool = (const int*)d_in[4];
    const float* W0 = (const float*)d_in[5];
    const float* b0 = (const float*)d_in[6];
    const float* W1 = (const float*)d_in[7];
    const float* b1 = (const float*)d_in[8];
    const float* W2 = (const float*)d_in[9];
    const float* b2 = (const float*)d_in[10];

    const int nf = in_sizes[0] / D;
    const int Ef = in_sizes[1] / 2;
    const int np = in_sizes[2] / D;
    const int Ep = in_sizes[3] / 2;
    float* out = (float*)d_out;

    __half *h1, *h2;
    float *buf2, *dinvf, *dinvp;
    int *cntf, *rpf, *curf, *esrcf, *esrcf2, *cntp, *rpp, *curp, *esrcp, *bsf, *bsp, *inv;
    unsigned char* wimg;
    cudaGetSymbolAddress((void**)&h1,     g_h1);
    cudaGetSymbolAddress((void**)&h2,     g_h2);
    cudaGetSymbolAddress((void**)&buf2,   g_buf2);
    cudaGetSymbolAddress((void**)&cntf,   g_cntf);
    cudaGetSymbolAddress((void**)&rpf,    g_rpf);
    cudaGetSymbolAddress((void**)&curf,   g_curf);
    cudaGetSymbolAddress((void**)&esrcf,  g_esrcf);
    cudaGetSymbolAddress((void**)&esrcf2, g_esrcf2);
    cudaGetSymbolAddress((void**)&dinvf,  g_dinvf);
    cudaGetSymbolAddress((void**)&cntp,   g_cntp);
    cudaGetSymbolAddress((void**)&rpp,    g_rpp);
    cudaGetSymbolAddress((void**)&curp,   g_curp);
    cudaGetSymbolAddress((void**)&esrcp,  g_esrcp);
    cudaGetSymbolAddress((void**)&dinvp,  g_dinvp);
    cudaGetSymbolAddress((void**)&inv,    g_inv);
    cudaGetSymbolAddress((void**)&bsf,    g_bsf);
    cudaGetSymbolAddress((void**)&bsp,    g_bsp);
    cudaGetSymbolAddress((void**)&wimg,   g_wimg);

    const int GEMM_SMEM = 96 * 1024;
    cudaFuncSetAttribute(k_gemm_mma, cudaFuncAttributeMaxDynamicSharedMemorySize, GEMM_SMEM);

    const unsigned char* img0h = wimg;
    const unsigned char* img0l = wimg + 32768;
    const unsigned char* img1h = wimg + 2 * 32768;
    const unsigned char* img1l = wimg + 3 * 32768;
    const unsigned char* img2h = wimg + 4 * 32768;
    const unsigned char* img2l = wimg + 5 * 32768;

    const int nbf = cdiv(nf, 1024), nbp = cdiv(np, 1024);

    static cudaStream_t s1 = nullptr, s2 = nullptr;
    static cudaEvent_t ev_fork = nullptr, ev_inv = nullptr, ev_pw = nullptr,
                       ev_g0 = nullptr, ev_dinv = nullptr, ev_place = nullptr;
    if (!s1) {
        cudaStreamCreateWithFlags(&s1, cudaStreamNonBlocking);
        cudaStreamCreateWithFlags(&s2, cudaStreamNonBlocking);
        cudaEventCreateWithFlags(&ev_fork, cudaEventDisableTiming);
        cudaEventCreateWithFlags(&ev_inv, cudaEventDisableTiming);
        cudaEventCreateWithFlags(&ev_pw, cudaEventDisableTiming);
        cudaEventCreateWithFlags(&ev_g0, cudaEventDisableTiming);
        cudaEventCreateWithFlags(&ev_dinv, cudaEventDisableTiming);
        cudaEventCreateWithFlags(&ev_place, cudaEventDisableTiming);
    }

    // ---- prologue (main stream) ----
    k_zero_prep<<<cdiv(nf, 256), 256>>>(cntf, cntp, inv, nf, np, W0, W1, W2);
    cudaEventRecord(ev_fork, 0);

    // main: pooled CSR first (dinvp needed by GEMM0 epilogue)
    k_hist<<<cdiv(Ep, 256), 256>>>(pei + Ep, Ep, cntp);
    k_bsum<<<nbp, 256>>>(cntp, np, bsp);
    k_write<<<nbp, 256>>>(cntp, np, bsp, nbp, rpp, curp, dinvp);
    cudaEventRecord(ev_pw, 0);
    k_place<<<cdiv(Ep, 256), 256>>>(pei, pei + Ep, Ep, curp, esrcp);

    // s1: inv index, then GEMM0 (px @ W0, scaled by dinvp) after pooled write
    cudaStreamWaitEvent(s1, ev_fork, 0);
    k_inv<<<cdiv(np, 256), 256, 0, s1>>>(unpool, inv, np);
    cudaEventRecord(ev_inv, s1);
    cudaStreamWaitEvent(s1, ev_pw, 0);
    k_gemm_mma<<<cdiv(np, 64), 256, GEMM_SMEM, s1>>>(px, img0h, img0l, h1, np, dinvp, nullptr);
    cudaEventRecord(ev_g0, s1);

    // s2: full-graph CSR; place also writes inv-mapped edge list
    cudaStreamWaitEvent(s2, ev_fork, 0);
    k_hist<<<cdiv(Ef, 256), 256, 0, s2>>>(ei + Ef, Ef, cntf);
    k_bsum<<<nbf, 256, 0, s2>>>(cntf, nf, bsf);
    k_write<<<nbf, 256, 0, s2>>>(cntf, nf, bsf, nbf, rpf, curf, dinvf);
    cudaEventRecord(ev_dinv, s2);
    cudaStreamWaitEvent(s2, ev_inv, 0);
    k_place2v<<<cdiv(Ef, 256), 256, 0, s2>>>(ei, ei + Ef, Ef, curf, esrcf, esrcf2, inv);
    cudaEventRecord(ev_place, s2);

    // conv0 gather (pre-scaled sources; needs GEMM0 + pooled place)
    cudaStreamWaitEvent(0, ev_g0, 0);
    k_gather_s<<<cdiv(np, 8), 256>>>(rpp, esrcp, dinvp, h1, b0, nullptr, buf2, np);

    // conv1: compact GEMM (needs dinvf); gather1 uses pre-mapped edges (needs place)
    cudaStreamWaitEvent(0, ev_dinv, 0);
    k_gemm_mma<<<cdiv(np, 64), 256, GEMM_SMEM>>>(buf2, img1h, img1l, h2, np, dinvf, unpool);
    cudaStreamWaitEvent(0, ev_place, 0);
    k_gather_s<<<cdiv(nf, 8), 256>>>(rpf, esrcf2, dinvf, h2, b1, inv, buf2, nf);

    // conv2: full GEMM (scale dinvf[row]) + raw-edge gather -> out
    k_gemm_mma<<<cdiv(nf, 64), 256, GEMM_SMEM>>>(buf2, img2h, img2l, h1, nf, dinvf, nullptr);
    k_gather_s<<<cdiv(nf, 8), 256>>>(rpf, esrcf, dinvf, h1, b2, nullptr, out, nf);
}